// round 17
// baseline (speedup 1.0000x reference)
#include <cuda_runtime.h>

// out[b, p, d] = x[b, p] * W[p, d] + bias[p, d]
// B=64, P=2000, D=512 (fp32). At the HBM write roofline (~6.7TB/s writes).
//
// Converged shape: thread = one (p,d4) float4 column x 8 batch rows,
// B_CHUNK=8, TPB=256, .cs stores (default 45.6us, .wt 45.8us both lose),
// 128-bit access (256-bit loses), HW scheduling (persistent loses).
//
// Final axis: CTA rasterization order. Grid swapped to (8, 1000) so
// blockIdx.x = batch chunk -> a concurrent wave spreads stores across all
// 64 batch slabs (vs 8), changing DRAM page/bank concurrency only.
// Per-thread work and instruction mix identical to the 39.4us kernel.

#define B_DIM 64
#define P_DIM 2000
#define D_DIM 512
#define D4 (D_DIM / 4)              // 128
#define PD4 (P_DIM * D4)            // 256000
#define B_CHUNK 8                   // batches per thread
#define N_CHUNKS (B_DIM / B_CHUNK)  // 8

__global__ __launch_bounds__(256) void feature_expander_kernel(
    const float* __restrict__ x,      // [B, P]
    const float4* __restrict__ W,     // [P, D/4]
    const float4* __restrict__ bias,  // [P, D/4]
    float4* __restrict__ out)         // [B, P, D/4]
{
    // Swapped: x = batch chunk (varies fastest), y = column strip.
    int idx = blockIdx.y * blockDim.x + threadIdx.x;   // < PD4 always (1000*256)
    int p = idx >> 7;                                  // idx / 128
    int b0 = blockIdx.x * B_CHUNK;

    float4 w = __ldg(&W[idx]);
    float4 bv = __ldg(&bias[idx]);

    const float* xp = x + b0 * P_DIM + p;
    float4* op = out + (size_t)b0 * PD4 + idx;

    #pragma unroll
    for (int i = 0; i < B_CHUNK; i++) {
        float xv = __ldg(xp + i * P_DIM);
        float4 o;
        o.x = fmaf(xv, w.x, bv.x);
        o.y = fmaf(xv, w.y, bv.y);
        o.z = fmaf(xv, w.z, bv.z);
        o.w = fmaf(xv, w.w, bv.w);
        __stcs(op + (size_t)i * PD4, o);   // streaming store (evict-first)
    }
}

extern "C" void kernel_launch(void* const* d_in, const int* in_sizes, int n_in,
                              void* d_out, int out_size) {
    const float*  x  = (const float*)d_in[0];
    const float4* W  = (const float4*)d_in[1];
    const float4* bb = (const float4*)d_in[2];
    float4* out = (float4*)d_out;

    dim3 grid(N_CHUNKS, PD4 / 256);   // 8 x 1000 (batch chunk fastest)
    feature_expander_kernel<<<grid, 256>>>(x, W, bb, out);
}